// round 2
// baseline (speedup 1.0000x reference)
#include <cuda_runtime.h>

// NCC loss, 9x9 box, SAME zero pad, n=81 (matches reference conv).
// Round 2: two rows per step, horizontal 9-tap products/sums computed with
// packed f32x2 FMA (Blackwell FFMA2) on row-pairs staged as u64 in smem.
// Vertical 9-row sliding window via scalar register ring (static indices).
// Deterministic two-stage reduction.

#define WW 512
#define HH 512
#define NB 32
#define COLS 128
#define NBLK (4 * 4 * 32)

__device__ float g_partials[NBLK];

__device__ __forceinline__ unsigned long long pk2(float lo, float hi) {
    unsigned long long v;
    asm("mov.b64 %0, {%1, %2};" : "=l"(v) : "f"(lo), "f"(hi));
    return v;
}
__device__ __forceinline__ void unpk2(unsigned long long v, float& lo, float& hi) {
    asm("mov.b64 {%0, %1}, %2;" : "=f"(lo), "=f"(hi) : "l"(v));
}
__device__ __forceinline__ unsigned long long fma2_(unsigned long long a,
                                                   unsigned long long b,
                                                   unsigned long long c) {
    unsigned long long d;
    asm("fma.rn.f32x2 %0, %1, %2, %3;" : "=l"(d) : "l"(a), "l"(b), "l"(c));
    return d;
}
__device__ __forceinline__ unsigned long long add2_(unsigned long long a,
                                                    unsigned long long b) {
    unsigned long long d;
    asm("add.rn.f32x2 %0, %1, %2;" : "=l"(d) : "l"(a), "l"(b));
    return d;
}

__global__ __launch_bounds__(128, 3)
void ncc_main(const float* __restrict__ img1,
              const float* __restrict__ img2,
              const float* __restrict__ fus)
{
    const int tid   = threadIdx.x;
    const int xbase = blockIdx.x * COLS;
    const int ybase = blockIdx.y * COLS;      // 128-row strips
    const int b     = blockIdx.z;

    const size_t base = (size_t)b * (size_t)(HH * WW);
    const float* p1 = img1 + base;
    const float* p2 = img2 + base;
    const float* pf = fus  + base;

    // Row-pair staging: each u64 packs (row_y, row_y+1) for one column.
    __shared__ unsigned long long rows2[2][3][COLS + 8];
    __shared__ float wsum[4];

    float ring[9][8];
    float S[8];
#pragma unroll
    for (int j = 0; j < 9; ++j)
#pragma unroll
        for (int q = 0; q < 8; ++q) ring[j][q] = 0.0f;
#pragma unroll
    for (int q = 0; q < 8; ++q) S[q] = 0.0f;

    float acc = 0.0f;
    const float inv_n = 1.0f / 81.0f;

    // 68 double-steps cover staged rows i = 0..135 (global ybase-4 .. ybase+131).
    // Loop shaped as 8 x 9 so ring indices (2dd)%9, (2dd+1)%9 are compile-time.
    for (int o = 0; o < 8; ++o) {
#pragma unroll
        for (int dd = 0; dd < 9; ++dd) {
            const int d = o * 9 + dd;
            if (d < 68) {
                const int i0 = 2 * d;
                const int r0 = ybase - 4 + i0;
                const int r1 = r0 + 1;
                const bool ok0 = (r0 >= 0) && (r0 < HH);
                const bool ok1 = (r1 >= 0) && (r1 < HH);
                const int buf = d & 1;

                // ---- stage packed row-pair (136 wide, zero-padded) ----
                {
                    const long off0 = (long)r0 * WW;
                    const long off1 = (long)r1 * WW;
                    int  gx = xbase - 4 + tid;
                    bool cok = (gx >= 0) && (gx < WW);
                    long i0x = off0 + gx, i1x = off1 + gx;
                    bool a0 = ok0 && cok, a1 = ok1 && cok;
                    float v0, v1;
                    v0 = a0 ? __ldg(p1 + i0x) : 0.0f;
                    v1 = a1 ? __ldg(p1 + i1x) : 0.0f;
                    rows2[buf][0][tid] = pk2(v0, v1);
                    v0 = a0 ? __ldg(p2 + i0x) : 0.0f;
                    v1 = a1 ? __ldg(p2 + i1x) : 0.0f;
                    rows2[buf][1][tid] = pk2(v0, v1);
                    v0 = a0 ? __ldg(pf + i0x) : 0.0f;
                    v1 = a1 ? __ldg(pf + i1x) : 0.0f;
                    rows2[buf][2][tid] = pk2(v0, v1);
                    if (tid < 8) {
                        int  pos = COLS + tid;          // 128..135
                        int  gx2 = xbase - 4 + pos;     // >= 124, upper check only
                        bool c2  = (gx2 < WW);
                        long j0 = off0 + gx2, j1 = off1 + gx2;
                        bool b0 = ok0 && c2, b1 = ok1 && c2;
                        v0 = b0 ? __ldg(p1 + j0) : 0.0f;
                        v1 = b1 ? __ldg(p1 + j1) : 0.0f;
                        rows2[buf][0][pos] = pk2(v0, v1);
                        v0 = b0 ? __ldg(p2 + j0) : 0.0f;
                        v1 = b1 ? __ldg(p2 + j1) : 0.0f;
                        rows2[buf][1][pos] = pk2(v0, v1);
                        v0 = b0 ? __ldg(pf + j0) : 0.0f;
                        v1 = b1 ? __ldg(pf + j1) : 0.0f;
                        rows2[buf][2][pos] = pk2(v0, v1);
                    }
                }
                __syncthreads();

                // ---- packed horizontal 9-tap sums (both rows at once) ----
                unsigned long long H0 = 0, H1 = 0, H2 = 0, H3 = 0;
                unsigned long long H4 = 0, H5 = 0, H6 = 0, H7 = 0;
#pragma unroll
                for (int k = 0; k < 9; ++k) {
                    unsigned long long a = rows2[buf][0][tid + k];
                    unsigned long long c = rows2[buf][1][tid + k];
                    unsigned long long f = rows2[buf][2][tid + k];
                    H0 = add2_(H0, a);
                    H1 = fma2_(a, a, H1);
                    H2 = fma2_(a, f, H2);
                    H3 = add2_(H3, c);
                    H4 = fma2_(c, c, H4);
                    H5 = fma2_(c, f, H5);
                    H6 = add2_(H6, f);
                    H7 = fma2_(f, f, H7);
                }
                float hl[8], hh[8];
                unpk2(H0, hl[0], hh[0]);
                unpk2(H1, hl[1], hh[1]);
                unpk2(H2, hl[2], hh[2]);
                unpk2(H3, hl[3], hh[3]);
                unpk2(H4, hl[4], hh[4]);
                unpk2(H5, hl[5], hh[5]);
                unpk2(H6, hl[6], hh[6]);
                unpk2(H7, hl[7], hh[7]);

                const int sA = (2 * dd) % 9;      // compile-time constants
                const int sB = (2 * dd + 1) % 9;
                const bool emit = (d >= 4) && (d < 68);  // rows i0,i1 in [8,135]

                // ---- row A: vertical slide + epilogue ----
#pragma unroll
                for (int q = 0; q < 8; ++q) {
                    S[q] += hl[q] - ring[sA][q];
                    ring[sA][q] = hl[q];
                }
                if (emit) {
                    float mA = S[0] * inv_n, mB = S[3] * inv_n, mJ = S[6] * inv_n;
                    float crossA = fmaf(-mA, S[6], S[2]);
                    float varA   = fmaf(-mA, S[0], S[1]);
                    float varJ   = fmaf(-mJ, S[6], S[7]);
                    float crossB = fmaf(-mB, S[6], S[5]);
                    float varB   = fmaf(-mB, S[3], S[4]);
                    float ccA = crossA * crossA * __fdividef(1.0f, fmaf(varA, varJ, 1e-5f));
                    float ccB = crossB * crossB * __fdividef(1.0f, fmaf(varB, varJ, 1e-5f));
                    acc += (2.0f - ccA - ccB);
                }

                // ---- row B: vertical slide + epilogue ----
#pragma unroll
                for (int q = 0; q < 8; ++q) {
                    S[q] += hh[q] - ring[sB][q];
                    ring[sB][q] = hh[q];
                }
                if (emit) {
                    float mA = S[0] * inv_n, mB = S[3] * inv_n, mJ = S[6] * inv_n;
                    float crossA = fmaf(-mA, S[6], S[2]);
                    float varA   = fmaf(-mA, S[0], S[1]);
                    float varJ   = fmaf(-mJ, S[6], S[7]);
                    float crossB = fmaf(-mB, S[6], S[5]);
                    float varB   = fmaf(-mB, S[3], S[4]);
                    float ccA = crossA * crossA * __fdividef(1.0f, fmaf(varA, varJ, 1e-5f));
                    float ccB = crossB * crossB * __fdividef(1.0f, fmaf(varB, varJ, 1e-5f));
                    acc += (2.0f - ccA - ccB);
                }
                __syncthreads();   // smem buffer reused at d+2
            }
        }
    }

    // ---- deterministic block reduction ----
#pragma unroll
    for (int off = 16; off > 0; off >>= 1)
        acc += __shfl_xor_sync(0xffffffffu, acc, off);
    if ((tid & 31) == 0) wsum[tid >> 5] = acc;
    __syncthreads();
    if (tid == 0) {
        float t = (wsum[0] + wsum[1]) + (wsum[2] + wsum[3]);
        int bidx = (blockIdx.z * 4 + blockIdx.y) * 4 + blockIdx.x;
        g_partials[bidx] = t;
    }
}

__global__ void ncc_reduce(float* __restrict__ out)
{
    __shared__ float s[NBLK];
    const int t = threadIdx.x;
    s[t] = g_partials[t];
    __syncthreads();
#pragma unroll
    for (int off = NBLK / 2; off > 0; off >>= 1) {
        if (t < off) s[t] += s[t + off];
        __syncthreads();
    }
    if (t == 0) {
        // mean(combined) = sum(2*combined) * 0.5 / 2^23 = total * 2^-24
        out[0] = s[0] * 5.9604644775390625e-08f;
    }
}

extern "C" void kernel_launch(void* const* d_in, const int* in_sizes, int n_in,
                              void* d_out, int out_size)
{
    (void)in_sizes; (void)n_in; (void)out_size;
    const float* img1 = (const float*)d_in[0];
    const float* img2 = (const float*)d_in[1];
    const float* fus  = (const float*)d_in[2];

    dim3 grid(4, 4, NB);
    ncc_main<<<grid, 128>>>(img1, img2, fus);
    ncc_reduce<<<1, NBLK>>>((float*)d_out);
}

// round 3
// speedup vs baseline: 1.0749x; 1.0749x over previous
#include <cuda_runtime.h>

// NCC loss, 9x9 box, SAME zero pad, n=81 (matches reference conv).
// Round 3: scalar math (Round-1 proven), restructured:
//   - 64-row strips -> 1024 blocks (load balance 6.92/SM)
//   - 3-row staging per ONE barrier (24 barriers total, was 288)
//   - single fused kernel: last-block reduction (threadfence + wrapping atomicInc)
// Deterministic: fixed-order partial summation, no float atomics.

#define WW 512
#define HH 512
#define NB 32
#define COLS 128
#define STRIPH 64
#define NBLK (4 * 8 * 32)   // 1024 blocks

__device__ float        g_partials[NBLK];
__device__ unsigned int g_count = 0;

__global__ __launch_bounds__(128, 4)
void ncc_fused(const float* __restrict__ img1,
               const float* __restrict__ img2,
               const float* __restrict__ fus,
               float* __restrict__ out)
{
    const int tid   = threadIdx.x;
    const int xbase = blockIdx.x * COLS;
    const int ybase = blockIdx.y * STRIPH;
    const int b     = blockIdx.z;

    const size_t base = (size_t)b * (size_t)(HH * WW);
    const float* p1 = img1 + base;
    const float* p2 = img2 + base;
    const float* pf = fus  + base;

    // stage = 3 rows x 3 images x 136 columns, double buffered (1 barrier/stage)
    __shared__ float rows[2][3][3][COLS + 8];
    __shared__ float red[4];
    __shared__ int   lastflag;

    // column predicates/offsets are loop-invariant
    const int  gx   = xbase - 4 + tid;
    const bool cok  = (gx >= 0) && (gx < WW);
    const int  gx2  = xbase + 124 + tid;          // halo, only tid<8 uses
    const bool cok2 = (gx2 < WW);

    float ring[9][8];
    float S[8];
#pragma unroll
    for (int j = 0; j < 9; ++j)
#pragma unroll
        for (int q = 0; q < 8; ++q) ring[j][q] = 0.0f;
#pragma unroll
    for (int q = 0; q < 8; ++q) S[q] = 0.0f;

    float acc = 0.0f;
    const float inv_n = 1.0f / 81.0f;

    // 72 row-steps (input rows ybase-4 .. ybase+67) = 24 stages of 3 rows.
    auto stage = [&](int s) {
        const int buf = s & 1;
        const int r0  = ybase - 4 + 3 * s;
#pragma unroll
        for (int jj = 0; jj < 3; ++jj) {
            const int  r   = r0 + jj;
            const bool rok = (r >= 0) && (r < HH);
            const long ro  = (long)r * WW;
            const bool ok  = rok && cok;
            rows[buf][0][jj][tid] = ok ? __ldg(p1 + ro + gx) : 0.0f;
            rows[buf][1][jj][tid] = ok ? __ldg(p2 + ro + gx) : 0.0f;
            rows[buf][2][jj][tid] = ok ? __ldg(pf + ro + gx) : 0.0f;
            if (tid < 8) {
                const bool ok2 = rok && cok2;
                const int  pos = COLS + tid;
                rows[buf][0][jj][pos] = ok2 ? __ldg(p1 + ro + gx2) : 0.0f;
                rows[buf][1][jj][pos] = ok2 ? __ldg(p2 + ro + gx2) : 0.0f;
                rows[buf][2][jj][pos] = ok2 ? __ldg(pf + ro + gx2) : 0.0f;
            }
        }
    };

    stage(0);
    __syncthreads();

    for (int a = 0; a < 8; ++a) {
#pragma unroll
        for (int g = 0; g < 3; ++g) {
            const int s   = 3 * a + g;
            const int buf = s & 1;
            if (s + 1 < 24) stage(s + 1);   // fill other buffer while we compute

#pragma unroll
            for (int j = 0; j < 3; ++j) {
                const int slot = 3 * g + j;       // static 0..8 (== (9a+slot)%9)
                const int i    = 9 * a + slot;    // row-step index 0..71

                // ---- horizontal 9-tap sums of the 8 fields ----
                float h0 = 0.f, h1 = 0.f, h2 = 0.f, h3 = 0.f;
                float h4 = 0.f, h5 = 0.f, h6 = 0.f, h7 = 0.f;
#pragma unroll
                for (int k = 0; k < 9; ++k) {
                    const float av = rows[buf][0][j][tid + k];
                    const float cv = rows[buf][1][j][tid + k];
                    const float fv = rows[buf][2][j][tid + k];
                    h0 += av;
                    h1 = fmaf(av, av, h1);
                    h2 = fmaf(av, fv, h2);
                    h3 += cv;
                    h4 = fmaf(cv, cv, h4);
                    h5 = fmaf(cv, fv, h5);
                    h6 += fv;
                    h7 = fmaf(fv, fv, h7);
                }
                const float h[8] = {h0, h1, h2, h3, h4, h5, h6, h7};

                // ---- vertical slide (static ring slot) ----
#pragma unroll
                for (int q = 0; q < 8; ++q) {
                    S[q] += h[q] - ring[slot][q];
                    ring[slot][q] = h[q];
                }

                // ---- emit output row y = ybase + i - 8 (i in [8,71]) ----
                if (i >= 8) {
                    const float mA = S[0] * inv_n;
                    const float mB = S[3] * inv_n;
                    const float mJ = S[6] * inv_n;
                    const float crossA = fmaf(-mA, S[6], S[2]);
                    const float varA   = fmaf(-mA, S[0], S[1]);
                    const float varJ   = fmaf(-mJ, S[6], S[7]);
                    const float crossB = fmaf(-mB, S[6], S[5]);
                    const float varB   = fmaf(-mB, S[3], S[4]);
                    const float ccA = crossA * crossA *
                                      __fdividef(1.0f, fmaf(varA, varJ, 1e-5f));
                    const float ccB = crossB * crossB *
                                      __fdividef(1.0f, fmaf(varB, varJ, 1e-5f));
                    acc += (2.0f - ccA - ccB);   // 2 * combined
                }
            }
            __syncthreads();   // buf consumed; safe for stage s+2 to rewrite it
        }
    }

    // ---- deterministic block reduction ----
#pragma unroll
    for (int off = 16; off > 0; off >>= 1)
        acc += __shfl_xor_sync(0xffffffffu, acc, off);
    if ((tid & 31) == 0) red[tid >> 5] = acc;
    __syncthreads();

    const int bidx = (blockIdx.z * 8 + blockIdx.y) * 4 + blockIdx.x;
    if (tid == 0) {
        g_partials[bidx] = (red[0] + red[1]) + (red[2] + red[3]);
        __threadfence();
        // wrapping atomicInc: counts 0..1023 then wraps to 0 -> graph-replay safe
        unsigned int old = atomicInc(&g_count, NBLK - 1);
        lastflag = (old == NBLK - 1);
    }
    __syncthreads();

    if (lastflag) {
        // fixed-order final sum: thread t owns partials[t + 128*m]
        float v = 0.0f;
#pragma unroll
        for (int m = 0; m < NBLK / 128; ++m)
            v += g_partials[tid + 128 * m];
#pragma unroll
        for (int off = 16; off > 0; off >>= 1)
            v += __shfl_xor_sync(0xffffffffu, v, off);
        if ((tid & 31) == 0) red[tid >> 5] = v;
        __syncthreads();
        if (tid == 0) {
            const float tot = (red[0] + red[1]) + (red[2] + red[3]);
            // mean(combined) = sum(2*combined) * 0.5 / 2^23 = tot * 2^-24
            out[0] = tot * 5.9604644775390625e-08f;
        }
    }
}

extern "C" void kernel_launch(void* const* d_in, const int* in_sizes, int n_in,
                              void* d_out, int out_size)
{
    (void)in_sizes; (void)n_in; (void)out_size;
    const float* img1 = (const float*)d_in[0];
    const float* img2 = (const float*)d_in[1];
    const float* fus  = (const float*)d_in[2];

    dim3 grid(4, 8, NB);   // 1024 blocks
    ncc_fused<<<grid, 128>>>(img1, img2, fus, (float*)d_out);
}

// round 4
// speedup vs baseline: 1.4262x; 1.3268x over previous
#include <cuda_runtime.h>
#include <cstdint>

// NCC loss, 9x9 box, SAME zero pad, n=81 (matches reference conv).
// Round 4: occupancy attack.
//   - cp.async (LDGSTS) 16B staging with zero-fill: no register transit,
//     no LDG->STS scoreboard chains, flat load distribution.
//   - triple-buffered stages (3 rows/stage), wait_group 1, 1 barrier/stage.
//   - __launch_bounds__(128, 5): 102-reg budget -> 5 blocks/SM (20 warps).
// Math identical to Round 1/3 (rel_err ~6e-8). Deterministic fused reduction.

#define WW 512
#define HH 512
#define NB 32
#define COLS 128
#define STRIPH 64
#define NBLK (4 * 8 * 32)   // 1024 blocks
#define NSTAGE 24           // 72 row-steps / 3 rows per stage
#define VECS_PER_STAGE 306  // 9 row-images * 34 float4

__device__ float        g_partials[NBLK];
__device__ unsigned int g_count = 0;

__device__ __forceinline__ void cp16(uint32_t dst, const float* src, bool ok) {
    asm volatile("cp.async.cg.shared.global [%0], [%1], 16, %2;"
                 :: "r"(dst), "l"(src), "r"(ok ? 16 : 0) : "memory");
}
__device__ __forceinline__ void cp_commit() {
    asm volatile("cp.async.commit_group;" ::: "memory");
}
__device__ __forceinline__ void cp_wait1() {
    asm volatile("cp.async.wait_group 1;" ::: "memory");
}

__global__ __launch_bounds__(128, 5)
void ncc_fused(const float* __restrict__ img1,
               const float* __restrict__ img2,
               const float* __restrict__ fus,
               float* __restrict__ out)
{
    const int tid   = threadIdx.x;
    const int xbase = blockIdx.x * COLS;
    const int ybase = blockIdx.y * STRIPH;
    const int b     = blockIdx.z;

    const size_t base = (size_t)b * (size_t)(HH * WW);
    const float* p1 = img1 + base;
    const float* p2 = img2 + base;
    const float* pf = fus  + base;

    // triple-buffered stage: 3 bufs x 9 row-images x 136 floats (544B rows, 16B aligned)
    __shared__ float rows[3][9][136];
    __shared__ float red[4];
    __shared__ int   lastflag;

    const uint32_t smem_rows = (uint32_t)__cvta_generic_to_shared(&rows[0][0][0]);

    // ---- stage s into buffer buf: 306 float4 cp.asyncs, flat over threads ----
    auto stage = [&](int s, int buf) {
        const int r0 = ybase - 4 + 3 * s;
#pragma unroll
        for (int it = 0; it < 3; ++it) {
            const int i = tid + 128 * it;
            if (i < VECS_PER_STAGE) {
                const int rowimg = i / 34;          // img*3 + jj
                const int vec    = i - rowimg * 34;
                const int img    = rowimg / 3;
                const int jj     = rowimg - img * 3;
                const int r      = r0 + jj;
                const int gx     = xbase - 4 + vec * 4;
                const bool ok    = (r >= 0) && (r < HH) && (gx >= 0) && (gx < WW);
                // clamped (always-legal) address; src_size=0 zero-fills when !ok
                const int rc  = r < 0 ? 0 : (r >= HH ? HH - 1 : r);
                const int gxc = gx < 0 ? 0 : (gx > WW - 4 ? WW - 4 : gx);
                const float* p = (img == 0) ? p1 : ((img == 1) ? p2 : pf);
                const float* src = p + (long)rc * WW + gxc;
                const uint32_t dst =
                    smem_rows + (uint32_t)(((buf * 9 + rowimg) * 136 + vec * 4) * 4);
                cp16(dst, src, ok);
            }
        }
        cp_commit();
    };

    float ring[9][8];
    float S[8];
#pragma unroll
    for (int j = 0; j < 9; ++j)
#pragma unroll
        for (int q = 0; q < 8; ++q) ring[j][q] = 0.0f;
#pragma unroll
    for (int q = 0; q < 8; ++q) S[q] = 0.0f;

    float acc = 0.0f;
    const float inv_n = 1.0f / 81.0f;

    stage(0, 0);
    stage(1, 1);

    for (int a = 0; a < 8; ++a) {
#pragma unroll
        for (int g = 0; g < 3; ++g) {
            const int s = 3 * a + g;          // buf = s % 3 = g (compile-time)
            cp_wait1();                        // stage s landed (<=1 group pending)
            __syncthreads();                   // visible to all; buf (s-1)%3 free
            if (s + 2 < NSTAGE) stage(s + 2, (g + 2) % 3);

#pragma unroll
            for (int j = 0; j < 3; ++j) {
                const int slot = 3 * g + j;    // static 0..8 == (9a+slot) % 9

                // ---- horizontal 9-tap sums of the 8 fields ----
                float h0 = 0.f, h1 = 0.f, h2 = 0.f, h3 = 0.f;
                float h4 = 0.f, h5 = 0.f, h6 = 0.f, h7 = 0.f;
#pragma unroll
                for (int k = 0; k < 9; ++k) {
                    const float av = rows[g][0 + j][tid + k];
                    const float cv = rows[g][3 + j][tid + k];
                    const float fv = rows[g][6 + j][tid + k];
                    h0 += av;
                    h1 = fmaf(av, av, h1);
                    h2 = fmaf(av, fv, h2);
                    h3 += cv;
                    h4 = fmaf(cv, cv, h4);
                    h5 = fmaf(cv, fv, h5);
                    h6 += fv;
                    h7 = fmaf(fv, fv, h7);
                }

                // ---- vertical slide (static ring slot) ----
                S[0] += h0 - ring[slot][0]; ring[slot][0] = h0;
                S[1] += h1 - ring[slot][1]; ring[slot][1] = h1;
                S[2] += h2 - ring[slot][2]; ring[slot][2] = h2;
                S[3] += h3 - ring[slot][3]; ring[slot][3] = h3;
                S[4] += h4 - ring[slot][4]; ring[slot][4] = h4;
                S[5] += h5 - ring[slot][5]; ring[slot][5] = h5;
                S[6] += h6 - ring[slot][6]; ring[slot][6] = h6;
                S[7] += h7 - ring[slot][7]; ring[slot][7] = h7;

                // ---- emit output row (row-step i = 9a+slot >= 8) ----
                if (a > 0 || slot >= 8) {
                    const float mA = S[0] * inv_n;
                    const float mB = S[3] * inv_n;
                    const float mJ = S[6] * inv_n;
                    const float crossA = fmaf(-mA, S[6], S[2]);
                    const float varA   = fmaf(-mA, S[0], S[1]);
                    const float varJ   = fmaf(-mJ, S[6], S[7]);
                    const float crossB = fmaf(-mB, S[6], S[5]);
                    const float varB   = fmaf(-mB, S[3], S[4]);
                    const float ccA = crossA * crossA *
                                      __fdividef(1.0f, fmaf(varA, varJ, 1e-5f));
                    const float ccB = crossB * crossB *
                                      __fdividef(1.0f, fmaf(varB, varJ, 1e-5f));
                    acc += (2.0f - ccA - ccB);   // 2 * combined
                }
            }
            __syncthreads();   // all done reading buf g before it is refilled (s+3)
        }
    }

    // ---- deterministic block reduction ----
#pragma unroll
    for (int off = 16; off > 0; off >>= 1)
        acc += __shfl_xor_sync(0xffffffffu, acc, off);
    if ((tid & 31) == 0) red[tid >> 5] = acc;
    __syncthreads();

    const int bidx = (blockIdx.z * 8 + blockIdx.y) * 4 + blockIdx.x;
    if (tid == 0) {
        g_partials[bidx] = (red[0] + red[1]) + (red[2] + red[3]);
        __threadfence();
        unsigned int old = atomicInc(&g_count, NBLK - 1);  // wraps: graph-replay safe
        lastflag = (old == NBLK - 1);
    }
    __syncthreads();

    if (lastflag) {
        float v = 0.0f;
#pragma unroll
        for (int m = 0; m < NBLK / 128; ++m)
            v += g_partials[tid + 128 * m];
#pragma unroll
        for (int off = 16; off > 0; off >>= 1)
            v += __shfl_xor_sync(0xffffffffu, v, off);
        if ((tid & 31) == 0) red[tid >> 5] = v;
        __syncthreads();
        if (tid == 0) {
            const float tot = (red[0] + red[1]) + (red[2] + red[3]);
            // mean(combined) = sum(2*combined) * 0.5 / 2^23 = tot * 2^-24
            out[0] = tot * 5.9604644775390625e-08f;
        }
    }
}

extern "C" void kernel_launch(void* const* d_in, const int* in_sizes, int n_in,
                              void* d_out, int out_size)
{
    (void)in_sizes; (void)n_in; (void)out_size;
    const float* img1 = (const float*)d_in[0];
    const float* img2 = (const float*)d_in[1];
    const float* fus  = (const float*)d_in[2];

    dim3 grid(4, 8, NB);   // 1024 blocks
    ncc_fused<<<grid, 128>>>(img1, img2, fus, (float*)d_out);
}